// round 5
// baseline (speedup 1.0000x reference)
#include <cuda_runtime.h>
#include <cuda_bf16.h>
#include <math.h>

// ForMicroLoss: l = sum_{pos} softplus(-x)/n_pos + sum_{neg} softplus(x)/n_neg
// pred_y: fp32 [N*K], true_y: int32 [N*K] (labels in {0,1})
// Streaming reduction: 512 MB read, 4 B write. Single fused kernel.
//
// Per-element identity (t = log(1+exp(-|x|)), relu = max(x,0)):
//   pos contribution: softplus(-x) = t + relu - x
//   neg contribution: softplus( x) = t + relu
// c = t + relu - (lbl ? x : 0) is correct either way; accumulate
// sum_all += c and sum_pos += (lbl ? c : 0); neg = all - pos.
//
// Grid = 148 SMs x 8 resident CTAs (regs=32 -> exactly 8 CTAs/SM) = one
// full wave, no wave quantization. 32-bit indexing throughout.

#define NSMS     148
#define NBLOCKS  (NSMS * 8)      // 1184: exactly one full wave
#define NTHREADS 256
#define TOTAL_T  (NBLOCKS * NTHREADS)

__device__ float g_all_part[NBLOCKS];
__device__ float g_pos_part[NBLOCKS];
__device__ int   g_cnt_part[NBLOCKS];
__device__ unsigned int g_ticket = 0;   // reset to 0 by the last block each call

__device__ __forceinline__ void accum_elem(float x, int lbl,
                                           float& all_acc, float& pos_acc) {
    float e    = __expf(-fabsf(x));          // FMUL + MUFU.EX2
    float t    = __logf(1.0f + e);           // FADD + MUFU.LG2 + FMUL
    float relu = fmaxf(x, 0.0f);
    float lx   = lbl ? x : 0.0f;
    float c    = t + relu - lx;
    all_acc += c;
    pos_acc += lbl ? c : 0.0f;
}

__global__ __launch_bounds__(NTHREADS)
void micro_loss_kernel(const float* __restrict__ pred,
                       const int*   __restrict__ lbl,
                       float* __restrict__ out,
                       int n)                      // n = 67,108,864 < 2^31
{
    const int tid    = blockIdx.x * NTHREADS + threadIdx.x;
    const int stride = TOTAL_T;                    // 303,104
    const int n4     = n >> 2;                     // 16,777,216

    const float4* __restrict__ pred4 = reinterpret_cast<const float4*>(pred);
    const int4*   __restrict__ lbl4  = reinterpret_cast<const int4*>(lbl);

    float all_acc = 0.0f, pos_acc = 0.0f;
    int cnt = 0;

    // Main loop, unrolled x4 with batched loads: 8 independent LDG.128s
    // in flight before any math (high MLP).
    int i = tid;
    for (; i + 3 * stride < n4; i += 4 * stride) {
        float4 p0 = pred4[i];
        float4 p1 = pred4[i +     stride];
        float4 p2 = pred4[i + 2 * stride];
        float4 p3 = pred4[i + 3 * stride];
        int4   l0 = lbl4 [i];
        int4   l1 = lbl4 [i +     stride];
        int4   l2 = lbl4 [i + 2 * stride];
        int4   l3 = lbl4 [i + 3 * stride];

        cnt += (l0.x + l0.y + l0.z + l0.w) + (l1.x + l1.y + l1.z + l1.w)
             + (l2.x + l2.y + l2.z + l2.w) + (l3.x + l3.y + l3.z + l3.w);

        accum_elem(p0.x, l0.x, all_acc, pos_acc);
        accum_elem(p0.y, l0.y, all_acc, pos_acc);
        accum_elem(p0.z, l0.z, all_acc, pos_acc);
        accum_elem(p0.w, l0.w, all_acc, pos_acc);
        accum_elem(p1.x, l1.x, all_acc, pos_acc);
        accum_elem(p1.y, l1.y, all_acc, pos_acc);
        accum_elem(p1.z, l1.z, all_acc, pos_acc);
        accum_elem(p1.w, l1.w, all_acc, pos_acc);
        accum_elem(p2.x, l2.x, all_acc, pos_acc);
        accum_elem(p2.y, l2.y, all_acc, pos_acc);
        accum_elem(p2.z, l2.z, all_acc, pos_acc);
        accum_elem(p2.w, l2.w, all_acc, pos_acc);
        accum_elem(p3.x, l3.x, all_acc, pos_acc);
        accum_elem(p3.y, l3.y, all_acc, pos_acc);
        accum_elem(p3.z, l3.z, all_acc, pos_acc);
        accum_elem(p3.w, l3.w, all_acc, pos_acc);
    }
    // Vec4 remainder (per-thread iteration counts differ by at most 1)
    for (; i < n4; i += stride) {
        float4 p = pred4[i];
        int4   l = lbl4[i];
        cnt += l.x + l.y + l.z + l.w;
        accum_elem(p.x, l.x, all_acc, pos_acc);
        accum_elem(p.y, l.y, all_acc, pos_acc);
        accum_elem(p.z, l.z, all_acc, pos_acc);
        accum_elem(p.w, l.w, all_acc, pos_acc);
    }
    // Scalar tail (n % 4 != 0) — not hit at this shape
    for (int j = (n4 << 2) + tid; j < n; j += stride) {
        float x = pred[j];
        int   l = lbl[j];
        cnt += l;
        accum_elem(x, l, all_acc, pos_acc);
    }

    // Warp reduce
    #pragma unroll
    for (int off = 16; off > 0; off >>= 1) {
        all_acc += __shfl_down_sync(0xffffffffu, all_acc, off);
        pos_acc += __shfl_down_sync(0xffffffffu, pos_acc, off);
        cnt     += __shfl_down_sync(0xffffffffu, cnt,     off);
    }

    // Block reduce
    __shared__ float s_all[NTHREADS / 32];
    __shared__ float s_pos[NTHREADS / 32];
    __shared__ int   s_cnt[NTHREADS / 32];
    __shared__ bool  s_is_last;
    int lane = threadIdx.x & 31;
    int warp = threadIdx.x >> 5;
    if (lane == 0) { s_all[warp] = all_acc; s_pos[warp] = pos_acc; s_cnt[warp] = cnt; }
    __syncthreads();
    if (warp == 0) {
        all_acc = (lane < NTHREADS / 32) ? s_all[lane] : 0.0f;
        pos_acc = (lane < NTHREADS / 32) ? s_pos[lane] : 0.0f;
        cnt     = (lane < NTHREADS / 32) ? s_cnt[lane] : 0;
        #pragma unroll
        for (int off = 4; off > 0; off >>= 1) {
            all_acc += __shfl_down_sync(0xffffffffu, all_acc, off);
            pos_acc += __shfl_down_sync(0xffffffffu, pos_acc, off);
            cnt     += __shfl_down_sync(0xffffffffu, cnt,     off);
        }
        if (lane == 0) {
            g_all_part[blockIdx.x] = all_acc;
            g_pos_part[blockIdx.x] = pos_acc;
            g_cnt_part[blockIdx.x] = cnt;
            __threadfence();                       // publish partials
            unsigned int t = atomicAdd(&g_ticket, 1u);
            s_is_last = (t == NBLOCKS - 1);
        }
    }
    __syncthreads();

    // Last block to finish performs the final reduction (deterministic:
    // values and reduction order are identical regardless of which block
    // executes this). No block ever waits on another — no deadlock risk.
    if (s_is_last) {
        __threadfence();
        float fa = 0.0f, fp = 0.0f;
        int   fc = 0;
        #pragma unroll
        for (int k = 0; k < (NBLOCKS + NTHREADS - 1) / NTHREADS; k++) {
            int idx = threadIdx.x + k * NTHREADS;
            if (idx < NBLOCKS) {
                fa += g_all_part[idx];
                fp += g_pos_part[idx];
                fc += g_cnt_part[idx];
            }
        }
        #pragma unroll
        for (int off = 16; off > 0; off >>= 1) {
            fa += __shfl_down_sync(0xffffffffu, fa, off);
            fp += __shfl_down_sync(0xffffffffu, fp, off);
            fc += __shfl_down_sync(0xffffffffu, fc, off);
        }
        __shared__ float f_all[NTHREADS / 32];
        __shared__ float f_pos[NTHREADS / 32];
        __shared__ int   f_cnt[NTHREADS / 32];
        if (lane == 0) { f_all[warp] = fa; f_pos[warp] = fp; f_cnt[warp] = fc; }
        __syncthreads();
        if (warp == 0) {
            fa = (lane < NTHREADS / 32) ? f_all[lane] : 0.0f;
            fp = (lane < NTHREADS / 32) ? f_pos[lane] : 0.0f;
            fc = (lane < NTHREADS / 32) ? f_cnt[lane] : 0;
            #pragma unroll
            for (int off = 4; off > 0; off >>= 1) {
                fa += __shfl_down_sync(0xffffffffu, fa, off);
                fp += __shfl_down_sync(0xffffffffu, fp, off);
                fc += __shfl_down_sync(0xffffffffu, fc, off);
            }
            if (lane == 0) {
                float neg_sum = fa - fp;
                float n_pos = (float)fc;
                float n_neg = (float)n - n_pos;
                out[0] = fp / n_pos + neg_sum / n_neg;
                g_ticket = 0;                      // re-arm for next replay
            }
        }
    }
}

extern "C" void kernel_launch(void* const* d_in, const int* in_sizes, int n_in,
                              void* d_out, int out_size) {
    const float* pred = (const float*)d_in[0];
    const int*   lbl  = (const int*)d_in[1];
    float* out = (float*)d_out;
    int n = in_sizes[0];

    micro_loss_kernel<<<NBLOCKS, NTHREADS>>>(pred, lbl, out, n);
}

// round 7
// speedup vs baseline: 1.1386x; 1.1386x over previous
#include <cuda_runtime.h>
#include <cuda_bf16.h>
#include <math.h>

// ForMicroLoss: l = sum_{pos} softplus(-x)/n_pos + sum_{neg} softplus(x)/n_neg
// pred_y: fp32 [N*K], true_y: int32 [N*K] (labels in {0,1})
// Streaming reduction: 512 MB read, 4 B write. Single fused kernel.
//
// Per-element identity (t = log(1+exp(-|x|)), relu = max(x,0)):
//   pos contribution: softplus(-x) = t + relu - x
//   neg contribution: softplus( x) = t + relu
// c = t + relu - lbl*x is correct either way (lbl in {0,1}); accumulate
// sum_all += c and sum_pos += (lbl ? c : 0); neg = all - pos.
//
// Occupancy contract: __launch_bounds__(256, 8) forces <=32 regs/thread so
// 148 SMs x 8 CTAs = 1184 blocks is exactly ONE full wave (R5 regression
// root-cause: regs crept to 36 -> 7 CTAs/SM -> ragged 1.14 waves).

#define NSMS     148
#define NBLOCKS  (NSMS * 8)      // 1184
#define NTHREADS 256
#define TOTAL_T  (NBLOCKS * NTHREADS)

__device__ float g_all_part[NBLOCKS];
__device__ float g_pos_part[NBLOCKS];
__device__ int   g_cnt_part[NBLOCKS];
__device__ unsigned int g_ticket = 0;   // reset to 0 by the last block each call

__device__ __forceinline__ void accum_elem(float x, int lbl,
                                           float& all_acc, float& pos_acc) {
    float e    = __expf(-fabsf(x));          // FMUL + MUFU.EX2
    float t    = __logf(1.0f + e);           // FADD + MUFU.LG2 + FMUL
    float relu = fmaxf(x, 0.0f);
    float c    = t + relu - x * (float)lbl;  // FFMA with I2F'd label
    all_acc += c;
    pos_acc += lbl ? c : 0.0f;               // predicated FADD
}

__global__ void __launch_bounds__(NTHREADS, 8)
micro_loss_kernel(const float* __restrict__ pred,
                  const int*   __restrict__ lbl,
                  float* __restrict__ out,
                  int n)                      // n = 67,108,864 < 2^31
{
    const int tid    = blockIdx.x * NTHREADS + threadIdx.x;
    const int stride = TOTAL_T;               // 303,104
    const int n4     = n >> 2;                // 16,777,216

    const float4* __restrict__ pred4 = reinterpret_cast<const float4*>(pred);
    const int4*   __restrict__ lbl4  = reinterpret_cast<const int4*>(lbl);

    float all_acc = 0.0f, pos_acc = 0.0f;
    int cnt = 0;

    // Main loop, unrolled x4 with batched loads: 8 independent LDG.128s
    // in flight before any math (high MLP).
    int i = tid;
    for (; i + 3 * stride < n4; i += 4 * stride) {
        float4 p0 = pred4[i];
        float4 p1 = pred4[i +     stride];
        float4 p2 = pred4[i + 2 * stride];
        float4 p3 = pred4[i + 3 * stride];
        int4   l0 = lbl4 [i];
        int4   l1 = lbl4 [i +     stride];
        int4   l2 = lbl4 [i + 2 * stride];
        int4   l3 = lbl4 [i + 3 * stride];

        cnt += (l0.x + l0.y + l0.z + l0.w) + (l1.x + l1.y + l1.z + l1.w)
             + (l2.x + l2.y + l2.z + l2.w) + (l3.x + l3.y + l3.z + l3.w);

        accum_elem(p0.x, l0.x, all_acc, pos_acc);
        accum_elem(p0.y, l0.y, all_acc, pos_acc);
        accum_elem(p0.z, l0.z, all_acc, pos_acc);
        accum_elem(p0.w, l0.w, all_acc, pos_acc);
        accum_elem(p1.x, l1.x, all_acc, pos_acc);
        accum_elem(p1.y, l1.y, all_acc, pos_acc);
        accum_elem(p1.z, l1.z, all_acc, pos_acc);
        accum_elem(p1.w, l1.w, all_acc, pos_acc);
        accum_elem(p2.x, l2.x, all_acc, pos_acc);
        accum_elem(p2.y, l2.y, all_acc, pos_acc);
        accum_elem(p2.z, l2.z, all_acc, pos_acc);
        accum_elem(p2.w, l2.w, all_acc, pos_acc);
        accum_elem(p3.x, l3.x, all_acc, pos_acc);
        accum_elem(p3.y, l3.y, all_acc, pos_acc);
        accum_elem(p3.z, l3.z, all_acc, pos_acc);
        accum_elem(p3.w, l3.w, all_acc, pos_acc);
    }
    // Vec4 remainder (per-thread iteration counts differ by at most 1)
    for (; i < n4; i += stride) {
        float4 p = pred4[i];
        int4   l = lbl4[i];
        cnt += l.x + l.y + l.z + l.w;
        accum_elem(p.x, l.x, all_acc, pos_acc);
        accum_elem(p.y, l.y, all_acc, pos_acc);
        accum_elem(p.z, l.z, all_acc, pos_acc);
        accum_elem(p.w, l.w, all_acc, pos_acc);
    }
    // Scalar tail (n % 4 != 0) — not hit at this shape
    for (int j = (n4 << 2) + tid; j < n; j += stride) {
        float x = pred[j];
        int   l = lbl[j];
        cnt += l;
        accum_elem(x, l, all_acc, pos_acc);
    }

    // Warp reduce
    #pragma unroll
    for (int off = 16; off > 0; off >>= 1) {
        all_acc += __shfl_down_sync(0xffffffffu, all_acc, off);
        pos_acc += __shfl_down_sync(0xffffffffu, pos_acc, off);
        cnt     += __shfl_down_sync(0xffffffffu, cnt,     off);
    }

    // Block reduce
    __shared__ float s_all[NTHREADS / 32];
    __shared__ float s_pos[NTHREADS / 32];
    __shared__ int   s_cnt[NTHREADS / 32];
    __shared__ bool  s_is_last;
    int lane = threadIdx.x & 31;
    int warp = threadIdx.x >> 5;
    if (lane == 0) { s_all[warp] = all_acc; s_pos[warp] = pos_acc; s_cnt[warp] = cnt; }
    __syncthreads();
    if (warp == 0) {
        all_acc = (lane < NTHREADS / 32) ? s_all[lane] : 0.0f;
        pos_acc = (lane < NTHREADS / 32) ? s_pos[lane] : 0.0f;
        cnt     = (lane < NTHREADS / 32) ? s_cnt[lane] : 0;
        #pragma unroll
        for (int off = 4; off > 0; off >>= 1) {
            all_acc += __shfl_down_sync(0xffffffffu, all_acc, off);
            pos_acc += __shfl_down_sync(0xffffffffu, pos_acc, off);
            cnt     += __shfl_down_sync(0xffffffffu, cnt,     off);
        }
        if (lane == 0) {
            g_all_part[blockIdx.x] = all_acc;
            g_pos_part[blockIdx.x] = pos_acc;
            g_cnt_part[blockIdx.x] = cnt;
            __threadfence();                       // publish partials
            unsigned int t = atomicAdd(&g_ticket, 1u);
            s_is_last = (t == NBLOCKS - 1);
        }
    }
    __syncthreads();

    // Last block to finish performs the final reduction (deterministic:
    // values and reduction order are identical regardless of which block
    // executes this). No block ever waits on another — no deadlock risk.
    if (s_is_last) {
        __threadfence();
        float fa = 0.0f, fp = 0.0f;
        int   fc = 0;
        for (int idx = threadIdx.x; idx < NBLOCKS; idx += NTHREADS) {
            fa += g_all_part[idx];
            fp += g_pos_part[idx];
            fc += g_cnt_part[idx];
        }
        #pragma unroll
        for (int off = 16; off > 0; off >>= 1) {
            fa += __shfl_down_sync(0xffffffffu, fa, off);
            fp += __shfl_down_sync(0xffffffffu, fp, off);
            fc += __shfl_down_sync(0xffffffffu, fc, off);
        }
        __shared__ float f_all[NTHREADS / 32];
        __shared__ float f_pos[NTHREADS / 32];
        __shared__ int   f_cnt[NTHREADS / 32];
        if (lane == 0) { f_all[warp] = fa; f_pos[warp] = fp; f_cnt[warp] = fc; }
        __syncthreads();
        if (warp == 0) {
            fa = (lane < NTHREADS / 32) ? f_all[lane] : 0.0f;
            fp = (lane < NTHREADS / 32) ? f_pos[lane] : 0.0f;
            fc = (lane < NTHREADS / 32) ? f_cnt[lane] : 0;
            #pragma unroll
            for (int off = 4; off > 0; off >>= 1) {
                fa += __shfl_down_sync(0xffffffffu, fa, off);
                fp += __shfl_down_sync(0xffffffffu, fp, off);
                fc += __shfl_down_sync(0xffffffffu, fc, off);
            }
            if (lane == 0) {
                float neg_sum = fa - fp;
                float n_pos = (float)fc;
                float n_neg = (float)n - n_pos;
                out[0] = fp / n_pos + neg_sum / n_neg;
                g_ticket = 0;                      // re-arm for next replay
            }
        }
    }
}

extern "C" void kernel_launch(void* const* d_in, const int* in_sizes, int n_in,
                              void* d_out, int out_size) {
    const float* pred = (const float*)d_in[0];
    const int*   lbl  = (const int*)d_in[1];
    float* out = (float*)d_out;
    int n = in_sizes[0];

    micro_loss_kernel<<<NBLOCKS, NTHREADS>>>(pred, lbl, out, n);
}

// round 9
// speedup vs baseline: 1.1390x; 1.0004x over previous
#include <cuda_runtime.h>
#include <cuda_bf16.h>
#include <math.h>

// ForMicroLoss: l = sum_{pos} softplus(-x)/n_pos + sum_{neg} softplus(x)/n_neg
// pred_y: fp32 [N*K], true_y: int32 [N*K] (labels in {0,1})
// Streaming reduction: 512 MB read, 4 B write. Single fused kernel.
//
// Per-element identity (t = log(1+exp(-|x|)), relu = max(x,0)):
//   pos contribution: softplus(-x) = t + relu - x
//   neg contribution: softplus( x) = t + relu
// c = t + relu - lbl*x is correct either way (lbl in {0,1}); accumulate
// sum_all += c and sum_pos += (lbl ? c : 0); neg = all - pos.
//
// Occupancy contract: __launch_bounds__(256, 8) forces <=32 regs/thread so
// 148 SMs x 8 CTAs = 1184 blocks is exactly ONE full wave (verified R7:
// regs=32, occ=98.5%).
//
// Experiment (unrun due to broker flake): __ldcs (evict-first streaming) on
// all bulk loads — data is touched exactly once; dead-on-arrival lines
// shouldn't occupy L2/L1 or generate eviction pressure in the LTS.

#define NSMS     148
#define NBLOCKS  (NSMS * 8)      // 1184
#define NTHREADS 256
#define TOTAL_T  (NBLOCKS * NTHREADS)

__device__ float g_all_part[NBLOCKS];
__device__ float g_pos_part[NBLOCKS];
__device__ int   g_cnt_part[NBLOCKS];
__device__ unsigned int g_ticket = 0;   // reset to 0 by the last block each call

__device__ __forceinline__ void accum_elem(float x, int lbl,
                                           float& all_acc, float& pos_acc) {
    float e    = __expf(-fabsf(x));          // FMUL + MUFU.EX2
    float t    = __logf(1.0f + e);           // FADD + MUFU.LG2 + FMUL
    float relu = fmaxf(x, 0.0f);
    float c    = t + relu - x * (float)lbl;  // FFMA with I2F'd label
    all_acc += c;
    pos_acc += lbl ? c : 0.0f;               // predicated FADD
}

__global__ void __launch_bounds__(NTHREADS, 8)
micro_loss_kernel(const float* __restrict__ pred,
                  const int*   __restrict__ lbl,
                  float* __restrict__ out,
                  int n)                      // n = 67,108,864 < 2^31
{
    const int tid    = blockIdx.x * NTHREADS + threadIdx.x;
    const int stride = TOTAL_T;               // 303,104
    const int n4     = n >> 2;                // 16,777,216

    const float4* __restrict__ pred4 = reinterpret_cast<const float4*>(pred);
    const int4*   __restrict__ lbl4  = reinterpret_cast<const int4*>(lbl);

    float all_acc = 0.0f, pos_acc = 0.0f;
    int cnt = 0;

    // Main loop, unrolled x4 with batched loads: 8 independent LDG.128s
    // (evict-first) in flight before any math (high MLP).
    int i = tid;
    for (; i + 3 * stride < n4; i += 4 * stride) {
        float4 p0 = __ldcs(pred4 + i);
        float4 p1 = __ldcs(pred4 + i +     stride);
        float4 p2 = __ldcs(pred4 + i + 2 * stride);
        float4 p3 = __ldcs(pred4 + i + 3 * stride);
        int4   l0 = __ldcs(lbl4  + i);
        int4   l1 = __ldcs(lbl4  + i +     stride);
        int4   l2 = __ldcs(lbl4  + i + 2 * stride);
        int4   l3 = __ldcs(lbl4  + i + 3 * stride);

        cnt += (l0.x + l0.y + l0.z + l0.w) + (l1.x + l1.y + l1.z + l1.w)
             + (l2.x + l2.y + l2.z + l2.w) + (l3.x + l3.y + l3.z + l3.w);

        accum_elem(p0.x, l0.x, all_acc, pos_acc);
        accum_elem(p0.y, l0.y, all_acc, pos_acc);
        accum_elem(p0.z, l0.z, all_acc, pos_acc);
        accum_elem(p0.w, l0.w, all_acc, pos_acc);
        accum_elem(p1.x, l1.x, all_acc, pos_acc);
        accum_elem(p1.y, l1.y, all_acc, pos_acc);
        accum_elem(p1.z, l1.z, all_acc, pos_acc);
        accum_elem(p1.w, l1.w, all_acc, pos_acc);
        accum_elem(p2.x, l2.x, all_acc, pos_acc);
        accum_elem(p2.y, l2.y, all_acc, pos_acc);
        accum_elem(p2.z, l2.z, all_acc, pos_acc);
        accum_elem(p2.w, l2.w, all_acc, pos_acc);
        accum_elem(p3.x, l3.x, all_acc, pos_acc);
        accum_elem(p3.y, l3.y, all_acc, pos_acc);
        accum_elem(p3.z, l3.z, all_acc, pos_acc);
        accum_elem(p3.w, l3.w, all_acc, pos_acc);
    }
    // Vec4 remainder (per-thread iteration counts differ by at most 1)
    for (; i < n4; i += stride) {
        float4 p = __ldcs(pred4 + i);
        int4   l = __ldcs(lbl4  + i);
        cnt += l.x + l.y + l.z + l.w;
        accum_elem(p.x, l.x, all_acc, pos_acc);
        accum_elem(p.y, l.y, all_acc, pos_acc);
        accum_elem(p.z, l.z, all_acc, pos_acc);
        accum_elem(p.w, l.w, all_acc, pos_acc);
    }
    // Scalar tail (n % 4 != 0) — not hit at this shape
    for (int j = (n4 << 2) + tid; j < n; j += stride) {
        float x = __ldcs(pred + j);
        int   l = __ldcs(lbl  + j);
        cnt += l;
        accum_elem(x, l, all_acc, pos_acc);
    }

    // Warp reduce
    #pragma unroll
    for (int off = 16; off > 0; off >>= 1) {
        all_acc += __shfl_down_sync(0xffffffffu, all_acc, off);
        pos_acc += __shfl_down_sync(0xffffffffu, pos_acc, off);
        cnt     += __shfl_down_sync(0xffffffffu, cnt,     off);
    }

    // Block reduce
    __shared__ float s_all[NTHREADS / 32];
    __shared__ float s_pos[NTHREADS / 32];
    __shared__ int   s_cnt[NTHREADS / 32];
    __shared__ bool  s_is_last;
    int lane = threadIdx.x & 31;
    int warp = threadIdx.x >> 5;
    if (lane == 0) { s_all[warp] = all_acc; s_pos[warp] = pos_acc; s_cnt[warp] = cnt; }
    __syncthreads();
    if (warp == 0) {
        all_acc = (lane < NTHREADS / 32) ? s_all[lane] : 0.0f;
        pos_acc = (lane < NTHREADS / 32) ? s_pos[lane] : 0.0f;
        cnt     = (lane < NTHREADS / 32) ? s_cnt[lane] : 0;
        #pragma unroll
        for (int off = 4; off > 0; off >>= 1) {
            all_acc += __shfl_down_sync(0xffffffffu, all_acc, off);
            pos_acc += __shfl_down_sync(0xffffffffu, pos_acc, off);
            cnt     += __shfl_down_sync(0xffffffffu, cnt,     off);
        }
        if (lane == 0) {
            g_all_part[blockIdx.x] = all_acc;
            g_pos_part[blockIdx.x] = pos_acc;
            g_cnt_part[blockIdx.x] = cnt;
            __threadfence();                       // publish partials
            unsigned int t = atomicAdd(&g_ticket, 1u);
            s_is_last = (t == NBLOCKS - 1);
        }
    }
    __syncthreads();

    // Last block to finish performs the final reduction (deterministic:
    // values and reduction order are identical regardless of which block
    // executes this). No block ever waits on another — no deadlock risk.
    if (s_is_last) {
        __threadfence();
        float fa = 0.0f, fp = 0.0f;
        int   fc = 0;
        for (int idx = threadIdx.x; idx < NBLOCKS; idx += NTHREADS) {
            fa += g_all_part[idx];
            fp += g_pos_part[idx];
            fc += g_cnt_part[idx];
        }
        #pragma unroll
        for (int off = 16; off > 0; off >>= 1) {
            fa += __shfl_down_sync(0xffffffffu, fa, off);
            fp += __shfl_down_sync(0xffffffffu, fp, off);
            fc += __shfl_down_sync(0xffffffffu, fc, off);
        }
        __shared__ float f_all[NTHREADS / 32];
        __shared__ float f_pos[NTHREADS / 32];
        __shared__ int   f_cnt[NTHREADS / 32];
        if (lane == 0) { f_all[warp] = fa; f_pos[warp] = fp; f_cnt[warp] = fc; }
        __syncthreads();
        if (warp == 0) {
            fa = (lane < NTHREADS / 32) ? f_all[lane] : 0.0f;
            fp = (lane < NTHREADS / 32) ? f_pos[lane] : 0.0f;
            fc = (lane < NTHREADS / 32) ? f_cnt[lane] : 0;
            #pragma unroll
            for (int off = 4; off > 0; off >>= 1) {
                fa += __shfl_down_sync(0xffffffffu, fa, off);
                fp += __shfl_down_sync(0xffffffffu, fp, off);
                fc += __shfl_down_sync(0xffffffffu, fc, off);
            }
            if (lane == 0) {
                float neg_sum = fa - fp;
                float n_pos = (float)fc;
                float n_neg = (float)n - n_pos;
                out[0] = fp / n_pos + neg_sum / n_neg;
                g_ticket = 0;                      // re-arm for next replay
            }
        }
    }
}

extern "C" void kernel_launch(void* const* d_in, const int* in_sizes, int n_in,
                              void* d_out, int out_size) {
    const float* pred = (const float*)d_in[0];
    const int*   lbl  = (const int*)d_in[1];
    float* out = (float*)d_out;
    int n = in_sizes[0];

    micro_loss_kernel<<<NBLOCKS, NTHREADS>>>(pred, lbl, out, n);
}